// round 12
// baseline (speedup 1.0000x reference)
#include <cuda_runtime.h>
#include <cuda_fp16.h>
#include <cuda_bf16.h>

#define NN 50000
#define EE 800000
#define HH 4

typedef unsigned long long ull;

// ---------------- scratch ----------------
__device__ __align__(16) __half g_xl1h[NN * 256];
__device__ __align__(16) __half g_xl2h[NN * 128];
__device__ __align__(16) float g_a1s[NN * 4];
__device__ __align__(16) float g_a1d[NN * 4];
__device__ __align__(16) float g_x2[NN * 64];
__device__ __align__(16) float g_a2s[NN * 4];
__device__ __align__(16) float g_a2d[NN * 4];
__device__ __align__(16) float g_ex2[EE * 4];
__device__ __align__(16) float g_den2[NN * 4];
__device__ __align__(16) __half g_pqh[NN * 128];
__device__ __align__(16) float g_wpq[32 * 128];
__device__ int  g_deg[NN];
__device__ int  g_ptr[NN];
__device__ int  g_pos[NN];
__device__ int  g_bsum[256];
__device__ __align__(8) int2 g_eid[EE];
__device__ int  g_arrive;
__device__ int  g_gen;

__device__ __forceinline__ ull ffma2(ull a, ull b, ull c) {
    ull d;
    asm("fma.rn.f32x2 %0, %1, %2, %3;" : "=l"(d) : "l"(a), "l"(b), "l"(c));
    return d;
}
__device__ __forceinline__ ull pack2(float x, float y) {
    ull d; asm("mov.b64 %0, {%1, %2};" : "=l"(d) : "f"(x), "f"(y)); return d;
}
__device__ __forceinline__ void unpack2(ull v, float& x, float& y) {
    asm("mov.b64 {%0, %1}, %2;" : "=f"(x), "=f"(y) : "l"(v));
}
__device__ __forceinline__ unsigned h2bits(float a, float b) {
    __half2 h = __floats2half2_rn(a, b);
    return *reinterpret_cast<unsigned*>(&h);
}
__device__ __forceinline__ float leaky_exp(float t) {
    t = fmaxf(t, 0.f) + 0.2f * fminf(t, 0.f);
    return __expf(t);
}
__device__ __forceinline__ unsigned tf32b(float f) {
    unsigned r; asm("cvt.rna.tf32.f32 %0, %1;" : "=r"(r) : "f"(f)); return r;
}

// ---------------- single-kernel CSR build (grid barrier; 296 co-resident blocks) ----------------
#define CSRB 296

__device__ __forceinline__ void gbar() {
    __syncthreads();
    if (threadIdx.x == 0) {
        volatile int* vgen = &g_gen;
        int gen = *vgen;
        __threadfence();
        if (atomicAdd(&g_arrive, 1) == CSRB - 1) {
            g_arrive = 0;
            __threadfence();
            atomicAdd(&g_gen, 1);
        } else {
            while (*vgen == gen) { }
        }
    }
    __syncthreads();
}

__global__ __launch_bounds__(256)
void csr_build(const int* __restrict__ src, const int* __restrict__ dst,
               int* __restrict__ deg, int* __restrict__ ptr, int* __restrict__ pos,
               int* __restrict__ bsum, int2* __restrict__ eid) {
    __shared__ int sm2[256];
    const int tid = threadIdx.x, b = blockIdx.x;
    const int gt = b * 256 + tid, gs = CSRB * 256;

    // P0: zero degree
    for (int i = gt; i < NN; i += gs) deg[i] = 0;
    gbar();
    // P1: histogram
    for (int e = gt; e < EE; e += gs) atomicAdd(&deg[dst[e]], 1);
    gbar();
    // P2: per-group (256-node) exclusive scan
    if (b < 196) {
        int node = b * 256 + tid;
        int v = (node < NN) ? deg[node] : 0;
        sm2[tid] = v; __syncthreads();
        for (int o = 1; o < 256; o <<= 1) {
            int t2 = (tid >= o) ? sm2[tid - o] : 0;
            __syncthreads(); sm2[tid] += t2; __syncthreads();
        }
        if (node < NN) ptr[node] = sm2[tid] - v;
        if (tid == 255) bsum[b] = sm2[255];
    }
    gbar();
    // P3: scan the 196 group sums (block 0)
    if (b == 0) {
        int v = (tid < 196) ? bsum[tid] : 0;
        sm2[tid] = v; __syncthreads();
        for (int o = 1; o < 256; o <<= 1) {
            int t2 = (tid >= o) ? sm2[tid - o] : 0;
            __syncthreads(); sm2[tid] += t2; __syncthreads();
        }
        if (tid < 196) bsum[tid] = sm2[tid] - v;
    }
    gbar();
    // P4: add group offsets
    for (int i = gt; i < NN; i += gs) {
        int v = ptr[i] + bsum[i >> 8];
        ptr[i] = v; pos[i] = v;
    }
    gbar();
    // P5: scatter edges (dst-sorted)
    for (int e = gt; e < EE; e += gs) {
        int p = atomicAdd(&pos[dst[e]], 1);
        eid[p] = make_int2(e, src[e]);
    }
}

// -------- repack mW1 rows {0..31}->cols 0..63, rows {36..67}->cols 64..127 --------
__global__ void repack_wpq(const float* __restrict__ mW1, float* __restrict__ wpq) {
    int idx = blockIdx.x * blockDim.x + threadIdx.x;
    if (idx >= 32 * 128) return;
    int k = idx / 128, j = idx % 128;
    wpq[idx] = (j < 64) ? mW1[k * 64 + j] : mW1[(36 + k) * 64 + (j - 64)];
}

// ---------------- gemm1 via tf32 mma.sync (R10 config): Y[N,256] = X[N,128] @ W1[128,256] ----------------
// 2D warp tiling: 8 warps = 2(m) x 4(n); each warp owns a 64x64 output tile.
// Double-buffered fragments with STATIC indices (k8 loop unrolled by 2).
#define SA 132
#define SB 264

#define LOAD_FRAGS(AF, BF, KC)                                              \
    do {                                                                    \
        int _kc = (KC);                                                     \
        _Pragma("unroll")                                                   \
        for (int mt = 0; mt < 4; mt++) {                                    \
            const float* ar = &Asm[(rwarp + mt * 16 + g) * SA + _kc];       \
            AF[mt][0] = __float_as_uint(ar[0]);                             \
            AF[mt][1] = __float_as_uint(ar[8 * SA]);                        \
            AF[mt][2] = __float_as_uint(ar[4]);                             \
            AF[mt][3] = __float_as_uint(ar[8 * SA + 4]);                    \
        }                                                                   \
        const float* br = &Bsm[(size_t)_kc * SB + cwarp + g];               \
        _Pragma("unroll")                                                   \
        for (int n8 = 0; n8 < 8; n8++) {                                    \
            BF[n8][0] = __float_as_uint(br[n8 * 8]);                        \
            BF[n8][1] = __float_as_uint(br[4 * SB + n8 * 8]);               \
        }                                                                   \
    } while (0)

#define MMA_FRAGS(AF, BF)                                                   \
    do {                                                                    \
        _Pragma("unroll")                                                   \
        for (int n8 = 0; n8 < 8; n8++)                                      \
            _Pragma("unroll")                                               \
            for (int mt = 0; mt < 4; mt++) {                                \
                asm volatile(                                               \
                    "mma.sync.aligned.m16n8k8.row.col.f32.tf32.tf32.f32 "  \
                    "{%0,%1,%2,%3}, {%4,%5,%6,%7}, {%8,%9}, {%0,%1,%2,%3};" \
                    : "+f"(acc[mt][n8][0]), "+f"(acc[mt][n8][1]),           \
                      "+f"(acc[mt][n8][2]), "+f"(acc[mt][n8][3])            \
                    : "r"(AF[mt][0]), "r"(AF[mt][1]),                       \
                      "r"(AF[mt][2]), "r"(AF[mt][3]),                       \
                      "r"(BF[n8][0]), "r"(BF[n8][1]));                      \
            }                                                               \
    } while (0)

__global__ __launch_bounds__(256, 1)
void gemm1_tf32(const float* __restrict__ X, const float* __restrict__ W,
                __half* __restrict__ Y,
                const float* __restrict__ att_s, const float* __restrict__ att_d,
                float* __restrict__ as_, float* __restrict__ ad_, int nN) {
    extern __shared__ float sm[];
    float* Asm = sm;                       // 128 x SA
    float* Bsm = sm + 128 * SA;            // 128 x SB
    float* satt = Bsm + 128 * SB;          // [0:256) att_s, [256:512) att_d
    const int tid = threadIdx.x;
    const int n0 = blockIdx.x * 128;
    const int nn = min(128, nN - n0);

    // fill A (X tile), tf32-rounded
    for (int i4 = tid; i4 < 128 * 32; i4 += 256) {
        int r = i4 >> 5, c4 = (i4 & 31) << 2;
        float4 v = (r < nn) ? *(const float4*)&X[(size_t)(n0 + r) * 128 + c4]
                            : make_float4(0.f, 0.f, 0.f, 0.f);
        uint4 u;
        u.x = tf32b(v.x); u.y = tf32b(v.y); u.z = tf32b(v.z); u.w = tf32b(v.w);
        *(uint4*)&Asm[r * SA + c4] = u;
    }
    // fill B (W1), tf32-rounded
    for (int i4 = tid; i4 < 128 * 64; i4 += 256) {
        int k = i4 >> 6, c4 = (i4 & 63) << 2;
        float4 v = *(const float4*)&W[k * 256 + c4];
        uint4 u;
        u.x = tf32b(v.x); u.y = tf32b(v.y); u.z = tf32b(v.z); u.w = tf32b(v.w);
        *(uint4*)&Bsm[k * SB + c4] = u;
    }
    satt[tid] = att_s[tid];
    satt[256 + tid] = att_d[tid];
    __syncthreads();

    const int w = tid >> 5, lane = tid & 31;
    const int g = lane >> 2, t = lane & 3;
    const int wm = w & 1, wn = w >> 1;           // 2 x 4 warp grid
    const int rwarp = wm * 64;                   // warp row base
    const int cwarp = wn * 64;                   // warp col base (== head wn * 64)

    float acc[4][8][4];
#pragma unroll
    for (int mt = 0; mt < 4; mt++)
#pragma unroll
        for (int n8 = 0; n8 < 8; n8++)
#pragma unroll
            for (int q = 0; q < 4; q++) acc[mt][n8][q] = 0.f;

    unsigned af0[4][4], bf0[8][2], af1[4][4], bf1[8][2];

    LOAD_FRAGS(af0, bf0, t);                       // k8 = 0
#pragma unroll 1
    for (int k8 = 0; k8 < 16; k8 += 2) {
        LOAD_FRAGS(af1, bf1, (k8 + 1) * 8 + t);    // prefetch odd stage
        MMA_FRAGS(af0, bf0);
        if (k8 + 2 < 16) LOAD_FRAGS(af0, bf0, (k8 + 2) * 8 + t);  // prefetch next even
        MMA_FRAGS(af1, bf1);
    }

    // ---- fused score epilogue: this warp's 64 cols == head wn ----
#pragma unroll
    for (int mt = 0; mt < 4; mt++) {
        float ps0 = 0.f, pd0 = 0.f, ps1 = 0.f, pd1 = 0.f;
#pragma unroll
        for (int n8 = 0; n8 < 8; n8++) {
            int col = cwarp + n8 * 8 + 2 * t;
            float s0 = satt[col], s1 = satt[col + 1];
            float d0 = satt[256 + col], d1 = satt[256 + col + 1];
            ps0 += acc[mt][n8][0] * s0 + acc[mt][n8][1] * s1;
            pd0 += acc[mt][n8][0] * d0 + acc[mt][n8][1] * d1;
            ps1 += acc[mt][n8][2] * s0 + acc[mt][n8][3] * s1;
            pd1 += acc[mt][n8][2] * d0 + acc[mt][n8][3] * d1;
        }
#pragma unroll
        for (int o = 1; o <= 2; o <<= 1) {
            ps0 += __shfl_xor_sync(0xffffffffu, ps0, o);
            pd0 += __shfl_xor_sync(0xffffffffu, pd0, o);
            ps1 += __shfl_xor_sync(0xffffffffu, ps1, o);
            pd1 += __shfl_xor_sync(0xffffffffu, pd1, o);
        }
        int m0 = n0 + rwarp + mt * 16 + g;
        int m1 = m0 + 8;
        if (t == 0) {
            if (m0 < nN) { as_[(size_t)m0 * 4 + wn] = ps0; ad_[(size_t)m0 * 4 + wn] = pd0; }
            if (m1 < nN) { as_[(size_t)m1 * 4 + wn] = ps1; ad_[(size_t)m1 * 4 + wn] = pd1; }
        }
        // ---- fp16 output for this mt ----
        bool w0 = (m0 < nN), w1 = (m1 < nN);
#pragma unroll
        for (int n8 = 0; n8 < 8; n8++) {
            int col = cwarp + n8 * 8 + 2 * t;
            if (w0) *(unsigned*)&Y[(size_t)m0 * 256 + col] = h2bits(acc[mt][n8][0], acc[mt][n8][1]);
            if (w1) *(unsigned*)&Y[(size_t)m1 * 256 + col] = h2bits(acc[mt][n8][2], acc[mt][n8][3]);
        }
    }
}

// ---------------- GEMM (FFMA2 path, used for layer2 + PQ): Y[N,M] = X[N,K] @ W[K,M] ----------------
template <int K, int M, int TN, int TH, int NSTEP, bool HALF_OUT, bool SC>
__launch_bounds__(TH, 1)
__global__ void gemm_xw(const float* __restrict__ X, const float* __restrict__ W,
                        void* __restrict__ Yv,
                        const float* __restrict__ att_s, const float* __restrict__ att_d,
                        float* __restrict__ as_, float* __restrict__ ad_, int nN) {
    extern __shared__ float sm[];
    constexpr int CG = M / 8;          // threads per node-row
    constexpr int PARTS = TH / CG;
    constexpr int NP = TN / PARTS;
    constexpr int HW = K * M / 2;
    static_assert(NP % NSTEP == 0, "NP % NSTEP");
    float* Xs = sm + K * M;            // [TN][K]
    const int tid = threadIdx.x;

    for (int i4 = tid; i4 < K * M / 4; i4 += TH) {
        int i = i4 * 4;
        int k = i / M, c = i % M;
        float4 v = *(const float4*)&W[i];
        int grp = (c >> 2) & 1;
        int d = (k * (M / 8) + (c >> 3)) * 4;
        *(float4*)&sm[(grp ? HW : 0) + d] = v;
    }
    const int n0 = blockIdx.x * TN;
    const int nn = min(TN, nN - n0);
    for (int i4 = tid; i4 < nn * K / 4; i4 += TH)
        ((float4*)Xs)[i4] = ((const float4*)(X + (size_t)n0 * K))[i4];
    __syncthreads();

    const int cg = tid % CG;
    const int part = tid / CG;
    const int nbase = part * NP;
    const ulonglong2* WA2 = (const ulonglong2*)sm;
    const ulonglong2* WB2 = (const ulonglong2*)(sm + HW);

    float4 avs0, avs1, avd0, avd1;
    if (SC) {
        avs0 = *(const float4*)&att_s[cg * 8];
        avs1 = *(const float4*)&att_s[cg * 8 + 4];
        avd0 = *(const float4*)&att_d[cg * 8];
        avd1 = *(const float4*)&att_d[cg * 8 + 4];
    }

    for (int nb = 0; nb < NP; nb += NSTEP) {
        ull a2[NSTEP][4];
#pragma unroll
        for (int j = 0; j < NSTEP; j++)
#pragma unroll
            for (int q = 0; q < 4; q++) a2[j][q] = 0ull;

#pragma unroll 2
        for (int k0 = 0; k0 < K; k0 += 4) {
            float4 xv[NSTEP];
#pragma unroll
            for (int j = 0; j < NSTEP; j++)
                xv[j] = *(const float4*)&Xs[(nbase + nb + j) * K + k0];
#pragma unroll
            for (int kk = 0; kk < 4; kk++) {
                ulonglong2 wA = WA2[(k0 + kk) * CG + cg];
                ulonglong2 wB = WB2[(k0 + kk) * CG + cg];
#pragma unroll
                for (int j = 0; j < NSTEP; j++) {
                    float xk = (kk == 0) ? xv[j].x : (kk == 1) ? xv[j].y
                             : (kk == 2) ? xv[j].z : xv[j].w;
                    ull xx = pack2(xk, xk);
                    a2[j][0] = ffma2(xx, wA.x, a2[j][0]);
                    a2[j][1] = ffma2(xx, wA.y, a2[j][1]);
                    a2[j][2] = ffma2(xx, wB.x, a2[j][2]);
                    a2[j][3] = ffma2(xx, wB.y, a2[j][3]);
                }
            }
        }
#pragma unroll
        for (int j = 0; j < NSTEP; j++) {
            int n = nbase + nb + j;
            float f0, f1, f2, f3, f4, f5, f6, f7;
            unpack2(a2[j][0], f0, f1); unpack2(a2[j][1], f2, f3);
            unpack2(a2[j][2], f4, f5); unpack2(a2[j][3], f6, f7);
            if (SC) {
                constexpr int C = M / 4;
                constexpr int RG = C / 8;    // lanes per head
                float ps = f0 * avs0.x + f1 * avs0.y + f2 * avs0.z + f3 * avs0.w
                         + f4 * avs1.x + f5 * avs1.y + f6 * avs1.z + f7 * avs1.w;
                float pd = f0 * avd0.x + f1 * avd0.y + f2 * avd0.z + f3 * avd0.w
                         + f4 * avd1.x + f5 * avd1.y + f6 * avd1.z + f7 * avd1.w;
#pragma unroll
                for (int o = 1; o < RG; o <<= 1) {
                    ps += __shfl_xor_sync(0xffffffffu, ps, o);
                    pd += __shfl_xor_sync(0xffffffffu, pd, o);
                }
                if ((cg & (RG - 1)) == 0 && n < nn) {
                    int h = (cg * 8) / C;
                    as_[(size_t)(n0 + n) * 4 + h] = ps;
                    ad_[(size_t)(n0 + n) * 4 + h] = pd;
                }
            }
            if (n < nn) {
                if (HALF_OUT) {
                    uint4 o;
                    o.x = h2bits(f0, f1); o.y = h2bits(f2, f3);
                    o.z = h2bits(f4, f5); o.w = h2bits(f6, f7);
                    ((uint4*)Yv)[(size_t)(n0 + n) * (M / 8) + cg] = o;
                } else {
                    float* yp = (float*)Yv + (size_t)(n0 + n) * M + cg * 8;
                    *(ulonglong2*)yp = make_ulonglong2(pack2(f0, f1), pack2(f2, f3));
                    *(ulonglong2*)(yp + 4) = make_ulonglong2(pack2(f4, f5), pack2(f6, f7));
                }
            }
        }
    }
}

// ---- CSR aggregation C=64 (layer 1): pipelined, fused exp + den + finalize ----
__launch_bounds__(256)
__global__ void agg_csr64(const int2* __restrict__ eid, const int* __restrict__ ptr,
                          const int* __restrict__ deg, const __half* __restrict__ xlh,
                          const float* __restrict__ as_, const float* __restrict__ ad_,
                          const float* __restrict__ bias, float* __restrict__ out) {
    int n = blockIdx.x * 8 + (threadIdx.x >> 5);
    if (n >= NN) return;
    int lane = threadIdx.x & 31;
    int h = lane >> 3;                    // head of this lane's 8 cols
    int p0 = ptr[n], dg = deg[n];
    float adh = ad_[(size_t)n * 4 + h];
    float acc[8];
#pragma unroll
    for (int i = 0; i < 8; i++) acc[i] = 0.f;
    float den = 0.f;
    const uint4* xl4 = (const uint4*)xlh;   // 32 uint4 per row

    int2 e0, e1;
    float a0;
    uint4 v0;
    if (dg > 0) {
        e0 = eid[p0];
        a0 = as_[(size_t)e0.y * 4 + h];
        v0 = xl4[(size_t)e0.y * 32 + lane];
        e1 = (dg > 1) ? eid[p0 + 1] : e0;
    }
    for (int j = 0; j < dg; j++) {
        float a1 = as_[(size_t)e1.y * 4 + h];
        uint4 v1 = xl4[(size_t)e1.y * 32 + lane];
        int2 e2 = (j + 2 < dg) ? eid[p0 + j + 2] : e1;
        float w = leaky_exp(a0 + adh);
        den += w;
        const __half2* hp = (const __half2*)&v0;
#pragma unroll
        for (int i = 0; i < 4; i++) {
            float2 f = __half22float2(hp[i]);
            acc[2 * i]     = fmaf(f.x, w, acc[2 * i]);
            acc[2 * i + 1] = fmaf(f.y, w, acc[2 * i + 1]);
        }
        a0 = a1; v0 = v1; e1 = e2;
    }
    float dh = 1.f / (den + 1e-16f);
#pragma unroll
    for (int i = 0; i < 8; i++) {
        acc[i] *= dh;
        acc[i] += __shfl_xor_sync(0xffffffffu, acc[i], 8);
        acc[i] += __shfl_xor_sync(0xffffffffu, acc[i], 16);
    }
    if (lane < 8) {
        float* op = out + (size_t)n * 64 + 8 * lane;
        const float* bp = bias + 8 * lane;
        float4 o0, o1;
        o0.x = 0.25f * acc[0] + bp[0]; o0.y = 0.25f * acc[1] + bp[1];
        o0.z = 0.25f * acc[2] + bp[2]; o0.w = 0.25f * acc[3] + bp[3];
        o1.x = 0.25f * acc[4] + bp[4]; o1.y = 0.25f * acc[5] + bp[5];
        o1.z = 0.25f * acc[6] + bp[6]; o1.w = 0.25f * acc[7] + bp[7];
        *(float4*)op = o0;
        *(float4*)(op + 4) = o1;
    }
}

// ---- CSR aggregation C=32 (layer 2): pipelined; exports ex2/den2 ----
__launch_bounds__(256)
__global__ void agg_csr32(const int2* __restrict__ eid, const int* __restrict__ ptr,
                          const int* __restrict__ deg, const __half* __restrict__ xlh,
                          const float* __restrict__ as_, const float* __restrict__ ad_,
                          const float* __restrict__ bias, float* __restrict__ out,
                          float* __restrict__ ex2, float* __restrict__ den2) {
    int n = blockIdx.x * 8 + (threadIdx.x >> 5);
    if (n >= NN) return;
    int lane = threadIdx.x & 31;
    int h = lane >> 3;                    // head of this lane's 4 cols
    int p0 = ptr[n], dg = deg[n];
    float adh = ad_[(size_t)n * 4 + h];
    float acc[4];
#pragma unroll
    for (int i = 0; i < 4; i++) acc[i] = 0.f;
    float den = 0.f;
    const uint2* xl2 = (const uint2*)xlh;   // 32 uint2 per row

    int2 e0, e1;
    float a0;
    uint2 v0;
    if (dg > 0) {
        e0 = eid[p0];
        a0 = as_[(size_t)e0.y * 4 + h];
        v0 = xl2[(size_t)e0.y * 32 + lane];
        e1 = (dg > 1) ? eid[p0 + 1] : e0;
    }
    for (int j = 0; j < dg; j++) {
        float a1 = as_[(size_t)e1.y * 4 + h];
        uint2 v1 = xl2[(size_t)e1.y * 32 + lane];
        int2 e2 = (j + 2 < dg) ? eid[p0 + j + 2] : e1;
        float w = leaky_exp(a0 + adh);
        den += w;
        if ((lane & 7) == 0) ex2[(size_t)e0.x * 4 + h] = w;   // export raw exp
        const __half2* hp = (const __half2*)&v0;
#pragma unroll
        for (int i = 0; i < 2; i++) {
            float2 f = __half22float2(hp[i]);
            acc[2 * i]     = fmaf(f.x, w, acc[2 * i]);
            acc[2 * i + 1] = fmaf(f.y, w, acc[2 * i + 1]);
        }
        e0 = e1; a0 = a1; v0 = v1; e1 = e2;
    }
    if ((lane & 7) == 0) den2[(size_t)n * 4 + h] = den;
    float dh = 1.f / (den + 1e-16f);
#pragma unroll
    for (int i = 0; i < 4; i++) {
        acc[i] *= dh;
        acc[i] += __shfl_xor_sync(0xffffffffu, acc[i], 8);
        acc[i] += __shfl_xor_sync(0xffffffffu, acc[i], 16);
    }
    if (lane < 8) {
        const float* bp = bias + 4 * lane;
        float4 o;
        o.x = 0.25f * acc[0] + bp[0]; o.y = 0.25f * acc[1] + bp[1];
        o.z = 0.25f * acc[2] + bp[2]; o.w = 0.25f * acc[3] + bp[3];
        *(float4*)(out + (size_t)n * 32 + 4 * lane) = o;
    }
}

// ---------------- edge MLP (decomposed, fp16 P/Q): relu(P[s]+Q[d]+alpha@B+b1) @ W2 ----------------
__launch_bounds__(256)
__global__ void edge_mlp2_kernel(const int* __restrict__ src, const int* __restrict__ dst,
                                 const __half* __restrict__ PQ,
                                 const float* __restrict__ ex2, const float* __restrict__ den2,
                                 const float* __restrict__ mW1, const float* __restrict__ mb1,
                                 const float* __restrict__ mW2, const float* __restrict__ mb2,
                                 float* __restrict__ eo) {
    __shared__ float W1B[4 * 64];   // rows 32..35 of mW1 (alpha part)
    __shared__ float B1[64];
    __shared__ ull W2p[64];         // (W2[j][0], W2[j][1]) pairs
    __shared__ float B2[2];
    int tid = threadIdx.x;
    for (int i = tid; i < 256; i += 256) W1B[i] = mW1[32 * 64 + i];
    if (tid < 64) B1[tid] = mb1[tid];
    if (tid < 128) ((float*)W2p)[tid] = mW2[tid];
    if (tid < 2) B2[tid] = mb2[tid];
    __syncthreads();

    int e = blockIdx.x * 256 + tid;
    if (e >= EE) return;
    int s = src[e], d = dst[e];

    float4 a4 = *(const float4*)(ex2 + (size_t)e * 4);
    float4 dn = *(const float4*)(den2 + (size_t)d * 4);
    float al0 = a4.x / (dn.x + 1e-16f);
    float al1 = a4.y / (dn.y + 1e-16f);
    float al2 = a4.z / (dn.z + 1e-16f);
    float al3 = a4.w / (dn.w + 1e-16f);

    const uint4* PQh = (const uint4*)PQ;  // 16 uint4 per node row (128 halves)
    size_t bs = (size_t)s * 16;           // P: cols 0..63  -> uint4 idx 0..7
    size_t bd = (size_t)d * 16 + 8;       // Q: cols 64..127 -> uint4 idx 0..7

    ull o2 = pack2(B2[0], B2[1]);
#pragma unroll
    for (int qq = 0; qq < 8; qq++) {
        uint4 ph = PQh[bs + qq];
        uint4 qh = PQh[bd + qq];
        const __half2* php = (const __half2*)&ph;
        const __half2* qhp = (const __half2*)&qh;
#pragma unroll
        for (int u2 = 0; u2 < 4; u2++) {
            float2 pf = __half22float2(php[u2]);
            float2 qf = __half22float2(qhp[u2]);
#pragma unroll
            for (int v = 0; v < 2; v++) {
                int j = 8 * qq + 2 * u2 + v;
                float hv = B1[j] + (v ? pf.y : pf.x) + (v ? qf.y : qf.x);
                hv = fmaf(al0, W1B[j], hv);
                hv = fmaf(al1, W1B[64 + j], hv);
                hv = fmaf(al2, W1B[128 + j], hv);
                hv = fmaf(al3, W1B[192 + j], hv);
                hv = fmaxf(hv, 0.f);
                o2 = ffma2(pack2(hv, hv), W2p[j], o2);
            }
        }
    }
    float o0, o1;
    unpack2(o2, o0, o1);
    ((float2*)eo)[e] = make_float2(o0, o1);
}

// ---------------- launch ----------------
extern "C" void kernel_launch(void* const* d_in, const int* in_sizes, int n_in,
                              void* d_out, int out_size) {
    const float* x    = (const float*)d_in[0];
    const int*   ei   = (const int*)d_in[1];
    const float* W1   = (const float*)d_in[4];
    const float* a1s  = (const float*)d_in[5];
    const float* a1d  = (const float*)d_in[6];
    const float* b1   = (const float*)d_in[7];
    const float* W3   = (const float*)d_in[8];
    const float* a3s  = (const float*)d_in[9];
    const float* a3d  = (const float*)d_in[10];
    const float* b3   = (const float*)d_in[11];
    const float* mW1  = (const float*)d_in[12];
    const float* mb1  = (const float*)d_in[13];
    const float* mW2  = (const float*)d_in[14];
    const float* mb2  = (const float*)d_in[15];

    const int* src = ei;
    const int* dst = ei + EE;

    float* out_nodes = (float*)d_out;             // N*32
    float* out_edges = (float*)d_out + NN * 32;   // E*2

    __half *p_xl1h, *p_xl2h, *p_pqh;
    float *p_x2, *p_a1s, *p_a1d, *p_a2s, *p_a2d, *p_ex2;
    float *p_den2, *p_wpq;
    int *p_deg, *p_ptr, *p_pos, *p_bsum;
    int2 *p_eid;
    cudaGetSymbolAddress((void**)&p_xl1h, g_xl1h);
    cudaGetSymbolAddress((void**)&p_xl2h, g_xl2h);
    cudaGetSymbolAddress((void**)&p_x2,  g_x2);
    cudaGetSymbolAddress((void**)&p_a1s, g_a1s);
    cudaGetSymbolAddress((void**)&p_a1d, g_a1d);
    cudaGetSymbolAddress((void**)&p_a2s, g_a2s);
    cudaGetSymbolAddress((void**)&p_a2d, g_a2d);
    cudaGetSymbolAddress((void**)&p_ex2, g_ex2);
    cudaGetSymbolAddress((void**)&p_den2, g_den2);
    cudaGetSymbolAddress((void**)&p_pqh, g_pqh);
    cudaGetSymbolAddress((void**)&p_wpq, g_wpq);
    cudaGetSymbolAddress((void**)&p_deg, g_deg);
    cudaGetSymbolAddress((void**)&p_ptr, g_ptr);
    cudaGetSymbolAddress((void**)&p_pos, g_pos);
    cudaGetSymbolAddress((void**)&p_bsum, g_bsum);
    cudaGetSymbolAddress((void**)&p_eid, g_eid);

    static cudaStream_t s2 = nullptr;
    static cudaEvent_t evFork = nullptr, evJoin = nullptr;
    if (!s2) {
        cudaStreamCreateWithFlags(&s2, cudaStreamNonBlocking);
        cudaEventCreateWithFlags(&evFork, cudaEventDisableTiming);
        cudaEventCreateWithFlags(&evJoin, cudaEventDisableTiming);
    }

    const int SMEM1 = (128 * SA + 128 * SB + 512) * 4;  // 204800 B

    cudaEventRecord(evFork, 0);                       // fork point
    cudaStreamWaitEvent(s2, evFork, 0);

    // main stream: single-kernel CSR build (k1)
    csr_build<<<CSRB, 256>>>(src, dst, p_deg, p_ptr, p_pos, p_bsum, p_eid);

    // side stream: gemm1 tf32 (k2) + repack (k3)
    cudaFuncSetAttribute((const void*)gemm1_tf32,
                         cudaFuncAttributeMaxDynamicSharedMemorySize, SMEM1);
    gemm1_tf32<<<(NN + 127) / 128, 256, SMEM1, s2>>>(
        x, W1, p_xl1h, a1s, a1d, p_a1s, p_a1d, NN);
    repack_wpq<<<(32 * 128 + 255) / 256, 256, 0, s2>>>(mW1, p_wpq);
    cudaEventRecord(evJoin, s2);

    cudaStreamWaitEvent(0, evJoin, 0);                // join

    // Layer 1 aggregation (k4 -> profiled)
    agg_csr64<<<(NN + 7) / 8, 256>>>(p_eid, p_ptr, p_deg, p_xl1h,
                                     p_a1s, p_a1d, b1, p_x2);

    // Layer 2 (k5, k6)
    cudaFuncSetAttribute((const void*)gemm_xw<64, 128, 128, 256, 8, true, true>,
                         cudaFuncAttributeMaxDynamicSharedMemorySize, 65536);
    gemm_xw<64, 128, 128, 256, 8, true, true><<<(NN + 127) / 128, 256, 65536>>>(
        p_x2, W3, p_xl2h, a3s, a3d, p_a2s, p_a2d, NN);
    agg_csr32<<<(NN + 7) / 8, 256>>>(p_eid, p_ptr, p_deg, p_xl2h,
                                     p_a2s, p_a2d, b3, out_nodes,
                                     p_ex2, p_den2);

    // Edge MLP (k7, k8)
    cudaFuncSetAttribute((const void*)gemm_xw<32, 128, 128, 256, 8, true, false>,
                         cudaFuncAttributeMaxDynamicSharedMemorySize, 32768);
    gemm_xw<32, 128, 128, 256, 8, true, false><<<(NN + 127) / 128, 256, 32768>>>(
        out_nodes, p_wpq, p_pqh, nullptr, nullptr, nullptr, nullptr, NN);
    edge_mlp2_kernel<<<(EE + 255) / 256, 256>>>(src, dst, p_pqh, p_ex2, p_den2,
                                                mW1, mb1, mW2, mb2, out_edges);
}

// round 13
// speedup vs baseline: 1.0828x; 1.0828x over previous
#include <cuda_runtime.h>
#include <cuda_fp16.h>
#include <cuda_bf16.h>

#define NN 50000
#define EE 800000
#define HH 4

typedef unsigned long long ull;

// ---------------- scratch ----------------
__device__ __align__(16) __half g_xl1h[NN * 256];
__device__ __align__(16) __half g_xl2h[NN * 128];
__device__ __align__(16) float g_a1s[NN * 4];
__device__ __align__(16) float g_a1d[NN * 4];
__device__ __align__(16) float g_x2[NN * 64];
__device__ __align__(16) float g_a2s[NN * 4];
__device__ __align__(16) float g_a2d[NN * 4];
__device__ __align__(16) float g_ex2[EE * 4];
__device__ __align__(16) float g_den2[NN * 4];
__device__ __align__(16) __half g_pqh[NN * 128];
__device__ __align__(16) float g_wpq[32 * 128];
__device__ int  g_deg[NN];
__device__ int  g_ptr[NN];
__device__ int  g_pos[NN];
__device__ int  g_bsum[128];
__device__ __align__(8) int2 g_eid[EE];

__device__ __forceinline__ ull ffma2(ull a, ull b, ull c) {
    ull d;
    asm("fma.rn.f32x2 %0, %1, %2, %3;" : "=l"(d) : "l"(a), "l"(b), "l"(c));
    return d;
}
__device__ __forceinline__ ull pack2(float x, float y) {
    ull d; asm("mov.b64 %0, {%1, %2};" : "=l"(d) : "f"(x), "f"(y)); return d;
}
__device__ __forceinline__ void unpack2(ull v, float& x, float& y) {
    asm("mov.b64 {%0, %1}, %2;" : "=f"(x), "=f"(y) : "l"(v));
}
__device__ __forceinline__ unsigned h2bits(float a, float b) {
    __half2 h = __floats2half2_rn(a, b);
    return *reinterpret_cast<unsigned*>(&h);
}
__device__ __forceinline__ float leaky_exp(float t) {
    t = fmaxf(t, 0.f) + 0.2f * fminf(t, 0.f);
    return __expf(t);
}
__device__ __forceinline__ unsigned tf32b(float f) {
    unsigned r; asm("cvt.rna.tf32.f32 %0, %1;" : "=r"(r) : "f"(f)); return r;
}

// ---------------- CSR build ----------------
__global__ void hist_kernel(const int* __restrict__ dst, int* __restrict__ deg) {
    int e = blockIdx.x * blockDim.x + threadIdx.x;
    if (e < EE) atomicAdd(&deg[dst[e]], 1);
}
__global__ void scanA_kernel(const int* __restrict__ deg, int* __restrict__ out,
                             int* __restrict__ bsum) {
    __shared__ int sm[512];
    int t = threadIdx.x;
    int g = blockIdx.x * 512 + t;
    int v = (g < NN) ? deg[g] : 0;
    sm[t] = v; __syncthreads();
    for (int o = 1; o < 512; o <<= 1) {
        int tt = (t >= o) ? sm[t - o] : 0;
        __syncthreads();
        sm[t] += tt;
        __syncthreads();
    }
    if (g < NN) out[g] = sm[t] - v;            // exclusive
    if (t == 511) bsum[blockIdx.x] = sm[511];
}
__global__ void scanB_kernel(int* __restrict__ bsum, int nb) {
    __shared__ int sm[128];
    int t = threadIdx.x;
    int v = (t < nb) ? bsum[t] : 0;
    sm[t] = v; __syncthreads();
    for (int o = 1; o < 128; o <<= 1) {
        int tt = (t >= o) ? sm[t - o] : 0;
        __syncthreads();
        sm[t] += tt;
        __syncthreads();
    }
    if (t < nb) bsum[t] = sm[t] - v;           // exclusive
}
__global__ void scanC_kernel(int* __restrict__ ptr, const int* __restrict__ bsum,
                             int* __restrict__ pos) {
    int g = blockIdx.x * 512 + threadIdx.x;
    if (g < NN) {
        int v = ptr[g] + bsum[blockIdx.x];
        ptr[g] = v;
        pos[g] = v;
    }
}
__global__ void scatter_kernel(const int* __restrict__ src, const int* __restrict__ dst,
                               int* __restrict__ pos, int2* __restrict__ eid) {
    int e = blockIdx.x * blockDim.x + threadIdx.x;
    if (e < EE) {
        int p = atomicAdd(&pos[dst[e]], 1);
        eid[p] = make_int2(e, src[e]);
    }
}

// -------- repack mW1 rows {0..31}->cols 0..63, rows {36..67}->cols 64..127 --------
__global__ void repack_wpq(const float* __restrict__ mW1, float* __restrict__ wpq) {
    int idx = blockIdx.x * blockDim.x + threadIdx.x;
    if (idx >= 32 * 128) return;
    int k = idx / 128, j = idx % 128;
    wpq[idx] = (j < 64) ? mW1[k * 64 + j] : mW1[(36 + k) * 64 + (j - 64)];
}

// ---------------- gemm1 via tf32 mma.sync (R10 config): Y[N,256] = X[N,128] @ W1[128,256] ----------------
#define SA 132
#define SB 264

#define LOAD_FRAGS(AF, BF, KC)                                              \
    do {                                                                    \
        int _kc = (KC);                                                     \
        _Pragma("unroll")                                                   \
        for (int mt = 0; mt < 4; mt++) {                                    \
            const float* ar = &Asm[(rwarp + mt * 16 + g) * SA + _kc];       \
            AF[mt][0] = __float_as_uint(ar[0]);                             \
            AF[mt][1] = __float_as_uint(ar[8 * SA]);                        \
            AF[mt][2] = __float_as_uint(ar[4]);                             \
            AF[mt][3] = __float_as_uint(ar[8 * SA + 4]);                    \
        }                                                                   \
        const float* br = &Bsm[(size_t)_kc * SB + cwarp + g];               \
        _Pragma("unroll")                                                   \
        for (int n8 = 0; n8 < 8; n8++) {                                    \
            BF[n8][0] = __float_as_uint(br[n8 * 8]);                        \
            BF[n8][1] = __float_as_uint(br[4 * SB + n8 * 8]);               \
        }                                                                   \
    } while (0)

#define MMA_FRAGS(AF, BF)                                                   \
    do {                                                                    \
        _Pragma("unroll")                                                   \
        for (int n8 = 0; n8 < 8; n8++)                                      \
            _Pragma("unroll")                                               \
            for (int mt = 0; mt < 4; mt++) {                                \
                asm volatile(                                               \
                    "mma.sync.aligned.m16n8k8.row.col.f32.tf32.tf32.f32 "  \
                    "{%0,%1,%2,%3}, {%4,%5,%6,%7}, {%8,%9}, {%0,%1,%2,%3};" \
                    : "+f"(acc[mt][n8][0]), "+f"(acc[mt][n8][1]),           \
                      "+f"(acc[mt][n8][2]), "+f"(acc[mt][n8][3])            \
                    : "r"(AF[mt][0]), "r"(AF[mt][1]),                       \
                      "r"(AF[mt][2]), "r"(AF[mt][3]),                       \
                      "r"(BF[n8][0]), "r"(BF[n8][1]));                      \
            }                                                               \
    } while (0)

__global__ __launch_bounds__(256, 1)
void gemm1_tf32(const float* __restrict__ X, const float* __restrict__ W,
                __half* __restrict__ Y,
                const float* __restrict__ att_s, const float* __restrict__ att_d,
                float* __restrict__ as_, float* __restrict__ ad_, int nN) {
    extern __shared__ float sm[];
    float* Asm = sm;                       // 128 x SA
    float* Bsm = sm + 128 * SA;            // 128 x SB
    float* satt = Bsm + 128 * SB;          // [0:256) att_s, [256:512) att_d
    const int tid = threadIdx.x;
    const int n0 = blockIdx.x * 128;
    const int nn = min(128, nN - n0);

    for (int i4 = tid; i4 < 128 * 32; i4 += 256) {
        int r = i4 >> 5, c4 = (i4 & 31) << 2;
        float4 v = (r < nn) ? *(const float4*)&X[(size_t)(n0 + r) * 128 + c4]
                            : make_float4(0.f, 0.f, 0.f, 0.f);
        uint4 u;
        u.x = tf32b(v.x); u.y = tf32b(v.y); u.z = tf32b(v.z); u.w = tf32b(v.w);
        *(uint4*)&Asm[r * SA + c4] = u;
    }
    for (int i4 = tid; i4 < 128 * 64; i4 += 256) {
        int k = i4 >> 6, c4 = (i4 & 63) << 2;
        float4 v = *(const float4*)&W[k * 256 + c4];
        uint4 u;
        u.x = tf32b(v.x); u.y = tf32b(v.y); u.z = tf32b(v.z); u.w = tf32b(v.w);
        *(uint4*)&Bsm[k * SB + c4] = u;
    }
    satt[tid] = att_s[tid];
    satt[256 + tid] = att_d[tid];
    __syncthreads();

    const int w = tid >> 5, lane = tid & 31;
    const int g = lane >> 2, t = lane & 3;
    const int wm = w & 1, wn = w >> 1;           // 2 x 4 warp grid
    const int rwarp = wm * 64;
    const int cwarp = wn * 64;

    float acc[4][8][4];
#pragma unroll
    for (int mt = 0; mt < 4; mt++)
#pragma unroll
        for (int n8 = 0; n8 < 8; n8++)
#pragma unroll
            for (int q = 0; q < 4; q++) acc[mt][n8][q] = 0.f;

    unsigned af0[4][4], bf0[8][2], af1[4][4], bf1[8][2];

    LOAD_FRAGS(af0, bf0, t);                       // k8 = 0
#pragma unroll 1
    for (int k8 = 0; k8 < 16; k8 += 2) {
        LOAD_FRAGS(af1, bf1, (k8 + 1) * 8 + t);
        MMA_FRAGS(af0, bf0);
        if (k8 + 2 < 16) LOAD_FRAGS(af0, bf0, (k8 + 2) * 8 + t);
        MMA_FRAGS(af1, bf1);
    }

#pragma unroll
    for (int mt = 0; mt < 4; mt++) {
        float ps0 = 0.f, pd0 = 0.f, ps1 = 0.f, pd1 = 0.f;
#pragma unroll
        for (int n8 = 0; n8 < 8; n8++) {
            int col = cwarp + n8 * 8 + 2 * t;
            float s0 = satt[col], s1 = satt[col + 1];
            float d0 = satt[256 + col], d1 = satt[256 + col + 1];
            ps0 += acc[mt][n8][0] * s0 + acc[mt][n8][1] * s1;
            pd0 += acc[mt][n8][0] * d0 + acc[mt][n8][1] * d1;
            ps1 += acc[mt][n8][2] * s0 + acc[mt][n8][3] * s1;
            pd1 += acc[mt][n8][2] * d0 + acc[mt][n8][3] * d1;
        }
#pragma unroll
        for (int o = 1; o <= 2; o <<= 1) {
            ps0 += __shfl_xor_sync(0xffffffffu, ps0, o);
            pd0 += __shfl_xor_sync(0xffffffffu, pd0, o);
            ps1 += __shfl_xor_sync(0xffffffffu, ps1, o);
            pd1 += __shfl_xor_sync(0xffffffffu, pd1, o);
        }
        int m0 = n0 + rwarp + mt * 16 + g;
        int m1 = m0 + 8;
        if (t == 0) {
            if (m0 < nN) { as_[(size_t)m0 * 4 + wn] = ps0; ad_[(size_t)m0 * 4 + wn] = pd0; }
            if (m1 < nN) { as_[(size_t)m1 * 4 + wn] = ps1; ad_[(size_t)m1 * 4 + wn] = pd1; }
        }
        bool w0 = (m0 < nN), w1 = (m1 < nN);
#pragma unroll
        for (int n8 = 0; n8 < 8; n8++) {
            int col = cwarp + n8 * 8 + 2 * t;
            if (w0) *(unsigned*)&Y[(size_t)m0 * 256 + col] = h2bits(acc[mt][n8][0], acc[mt][n8][1]);
            if (w1) *(unsigned*)&Y[(size_t)m1 * 256 + col] = h2bits(acc[mt][n8][2], acc[mt][n8][3]);
        }
    }
}

// ---------------- GEMM (FFMA2 path, used for layer2 + PQ): Y[N,M] = X[N,K] @ W[K,M] ----------------
template <int K, int M, int TN, int TH, int NSTEP, bool HALF_OUT, bool SC>
__launch_bounds__(TH, 1)
__global__ void gemm_xw(const float* __restrict__ X, const float* __restrict__ W,
                        void* __restrict__ Yv,
                        const float* __restrict__ att_s, const float* __restrict__ att_d,
                        float* __restrict__ as_, float* __restrict__ ad_, int nN) {
    extern __shared__ float sm[];
    constexpr int CG = M / 8;
    constexpr int PARTS = TH / CG;
    constexpr int NP = TN / PARTS;
    constexpr int HW = K * M / 2;
    static_assert(NP % NSTEP == 0, "NP % NSTEP");
    float* Xs = sm + K * M;
    const int tid = threadIdx.x;

    for (int i4 = tid; i4 < K * M / 4; i4 += TH) {
        int i = i4 * 4;
        int k = i / M, c = i % M;
        float4 v = *(const float4*)&W[i];
        int grp = (c >> 2) & 1;
        int d = (k * (M / 8) + (c >> 3)) * 4;
        *(float4*)&sm[(grp ? HW : 0) + d] = v;
    }
    const int n0 = blockIdx.x * TN;
    const int nn = min(TN, nN - n0);
    for (int i4 = tid; i4 < nn * K / 4; i4 += TH)
        ((float4*)Xs)[i4] = ((const float4*)(X + (size_t)n0 * K))[i4];
    __syncthreads();

    const int cg = tid % CG;
    const int part = tid / CG;
    const int nbase = part * NP;
    const ulonglong2* WA2 = (const ulonglong2*)sm;
    const ulonglong2* WB2 = (const ulonglong2*)(sm + HW);

    float4 avs0, avs1, avd0, avd1;
    if (SC) {
        avs0 = *(const float4*)&att_s[cg * 8];
        avs1 = *(const float4*)&att_s[cg * 8 + 4];
        avd0 = *(const float4*)&att_d[cg * 8];
        avd1 = *(const float4*)&att_d[cg * 8 + 4];
    }

    for (int nb = 0; nb < NP; nb += NSTEP) {
        ull a2[NSTEP][4];
#pragma unroll
        for (int j = 0; j < NSTEP; j++)
#pragma unroll
            for (int q = 0; q < 4; q++) a2[j][q] = 0ull;

#pragma unroll 2
        for (int k0 = 0; k0 < K; k0 += 4) {
            float4 xv[NSTEP];
#pragma unroll
            for (int j = 0; j < NSTEP; j++)
                xv[j] = *(const float4*)&Xs[(nbase + nb + j) * K + k0];
#pragma unroll
            for (int kk = 0; kk < 4; kk++) {
                ulonglong2 wA = WA2[(k0 + kk) * CG + cg];
                ulonglong2 wB = WB2[(k0 + kk) * CG + cg];
#pragma unroll
                for (int j = 0; j < NSTEP; j++) {
                    float xk = (kk == 0) ? xv[j].x : (kk == 1) ? xv[j].y
                             : (kk == 2) ? xv[j].z : xv[j].w;
                    ull xx = pack2(xk, xk);
                    a2[j][0] = ffma2(xx, wA.x, a2[j][0]);
                    a2[j][1] = ffma2(xx, wA.y, a2[j][1]);
                    a2[j][2] = ffma2(xx, wB.x, a2[j][2]);
                    a2[j][3] = ffma2(xx, wB.y, a2[j][3]);
                }
            }
        }
#pragma unroll
        for (int j = 0; j < NSTEP; j++) {
            int n = nbase + nb + j;
            float f0, f1, f2, f3, f4, f5, f6, f7;
            unpack2(a2[j][0], f0, f1); unpack2(a2[j][1], f2, f3);
            unpack2(a2[j][2], f4, f5); unpack2(a2[j][3], f6, f7);
            if (SC) {
                constexpr int C = M / 4;
                constexpr int RG = C / 8;
                float ps = f0 * avs0.x + f1 * avs0.y + f2 * avs0.z + f3 * avs0.w
                         + f4 * avs1.x + f5 * avs1.y + f6 * avs1.z + f7 * avs1.w;
                float pd = f0 * avd0.x + f1 * avd0.y + f2 * avd0.z + f3 * avd0.w
                         + f4 * avd1.x + f5 * avd1.y + f6 * avd1.z + f7 * avd1.w;
#pragma unroll
                for (int o = 1; o < RG; o <<= 1) {
                    ps += __shfl_xor_sync(0xffffffffu, ps, o);
                    pd += __shfl_xor_sync(0xffffffffu, pd, o);
                }
                if ((cg & (RG - 1)) == 0 && n < nn) {
                    int h = (cg * 8) / C;
                    as_[(size_t)(n0 + n) * 4 + h] = ps;
                    ad_[(size_t)(n0 + n) * 4 + h] = pd;
                }
            }
            if (n < nn) {
                if (HALF_OUT) {
                    uint4 o;
                    o.x = h2bits(f0, f1); o.y = h2bits(f2, f3);
                    o.z = h2bits(f4, f5); o.w = h2bits(f6, f7);
                    ((uint4*)Yv)[(size_t)(n0 + n) * (M / 8) + cg] = o;
                } else {
                    float* yp = (float*)Yv + (size_t)(n0 + n) * M + cg * 8;
                    *(ulonglong2*)yp = make_ulonglong2(pack2(f0, f1), pack2(f2, f3));
                    *(ulonglong2*)(yp + 4) = make_ulonglong2(pack2(f4, f5), pack2(f6, f7));
                }
            }
        }
    }
}

// ---- CSR aggregation C=64 (layer 1): straight-line loop, f32x2 accumulate ----
__launch_bounds__(256)
__global__ void agg_csr64(const int2* __restrict__ eid, const int* __restrict__ ptr,
                          const int* __restrict__ deg, const __half* __restrict__ xlh,
                          const float* __restrict__ as_, const float* __restrict__ ad_,
                          const float* __restrict__ bias, float* __restrict__ out) {
    int n = blockIdx.x * 8 + (threadIdx.x >> 5);
    if (n >= NN) return;
    int lane = threadIdx.x & 31;
    int h = lane >> 3;                    // head of this lane's 8 cols
    int p0 = ptr[n], dg = deg[n];
    float adh = ad_[(size_t)n * 4 + h];
    ull acc2[4];
#pragma unroll
    for (int i = 0; i < 4; i++) acc2[i] = 0ull;
    float den = 0.f;
    const uint4* xl4 = (const uint4*)xlh;   // 32 uint4 per row

    for (int j = 0; j < dg; j++) {
        int2 e = eid[p0 + j];
        float w = leaky_exp(as_[(size_t)e.y * 4 + h] + adh);
        den += w;
        uint4 v = xl4[(size_t)e.y * 32 + lane];
        ull ww = pack2(w, w);
        const __half2* hp = (const __half2*)&v;
#pragma unroll
        for (int i = 0; i < 4; i++) {
            float2 f = __half22float2(hp[i]);
            acc2[i] = ffma2(pack2(f.x, f.y), ww, acc2[i]);
        }
    }
    float acc[8];
#pragma unroll
    for (int i = 0; i < 4; i++) unpack2(acc2[i], acc[2 * i], acc[2 * i + 1]);
    float dh = 1.f / (den + 1e-16f);
#pragma unroll
    for (int i = 0; i < 8; i++) {
        acc[i] *= dh;
        acc[i] += __shfl_xor_sync(0xffffffffu, acc[i], 8);
        acc[i] += __shfl_xor_sync(0xffffffffu, acc[i], 16);
    }
    if (lane < 8) {
        float* op = out + (size_t)n * 64 + 8 * lane;
        const float* bp = bias + 8 * lane;
        float4 o0, o1;
        o0.x = 0.25f * acc[0] + bp[0]; o0.y = 0.25f * acc[1] + bp[1];
        o0.z = 0.25f * acc[2] + bp[2]; o0.w = 0.25f * acc[3] + bp[3];
        o1.x = 0.25f * acc[4] + bp[4]; o1.y = 0.25f * acc[5] + bp[5];
        o1.z = 0.25f * acc[6] + bp[6]; o1.w = 0.25f * acc[7] + bp[7];
        *(float4*)op = o0;
        *(float4*)(op + 4) = o1;
    }
}

// ---- CSR aggregation C=32 (layer 2): straight-line loop, f32x2 accumulate; exports ex2/den2 ----
__launch_bounds__(256)
__global__ void agg_csr32(const int2* __restrict__ eid, const int* __restrict__ ptr,
                          const int* __restrict__ deg, const __half* __restrict__ xlh,
                          const float* __restrict__ as_, const float* __restrict__ ad_,
                          const float* __restrict__ bias, float* __restrict__ out,
                          float* __restrict__ ex2, float* __restrict__ den2) {
    int n = blockIdx.x * 8 + (threadIdx.x >> 5);
    if (n >= NN) return;
    int lane = threadIdx.x & 31;
    int h = lane >> 3;                    // head of this lane's 4 cols
    int p0 = ptr[n], dg = deg[n];
    float adh = ad_[(size_t)n * 4 + h];
    ull acc2[2];
    acc2[0] = 0ull; acc2[1] = 0ull;
    float den = 0.f;
    const uint2* xl2 = (const uint2*)xlh;   // 32 uint2 per row

    for (int j = 0; j < dg; j++) {
        int2 e = eid[p0 + j];
        float w = leaky_exp(as_[(size_t)e.y * 4 + h] + adh);
        den += w;
        if ((lane & 7) == 0) ex2[(size_t)e.x * 4 + h] = w;   // export raw exp
        uint2 v = xl2[(size_t)e.y * 32 + lane];
        ull ww = pack2(w, w);
        const __half2* hp = (const __half2*)&v;
#pragma unroll
        for (int i = 0; i < 2; i++) {
            float2 f = __half22float2(hp[i]);
            acc2[i] = ffma2(pack2(f.x, f.y), ww, acc2[i]);
        }
    }
    if ((lane & 7) == 0) den2[(size_t)n * 4 + h] = den;
    float acc[4];
    unpack2(acc2[0], acc[0], acc[1]);
    unpack2(acc2[1], acc[2], acc[3]);
    float dh = 1.f / (den + 1e-16f);
#pragma unroll
    for (int i = 0; i < 4; i++) {
        acc[i] *= dh;
        acc[i] += __shfl_xor_sync(0xffffffffu, acc[i], 8);
        acc[i] += __shfl_xor_sync(0xffffffffu, acc[i], 16);
    }
    if (lane < 8) {
        const float* bp = bias + 4 * lane;
        float4 o;
        o.x = 0.25f * acc[0] + bp[0]; o.y = 0.25f * acc[1] + bp[1];
        o.z = 0.25f * acc[2] + bp[2]; o.w = 0.25f * acc[3] + bp[3];
        *(float4*)(out + (size_t)n * 32 + 4 * lane) = o;
    }
}

// ---------------- edge MLP (decomposed, fp16 P/Q): relu(P[s]+Q[d]+alpha@B+b1) @ W2 ----------------
__launch_bounds__(256)
__global__ void edge_mlp2_kernel(const int* __restrict__ src, const int* __restrict__ dst,
                                 const __half* __restrict__ PQ,
                                 const float* __restrict__ ex2, const float* __restrict__ den2,
                                 const float* __restrict__ mW1, const float* __restrict__ mb1,
                                 const float* __restrict__ mW2, const float* __restrict__ mb2,
                                 float* __restrict__ eo) {
    __shared__ float W1B[4 * 64];   // rows 32..35 of mW1 (alpha part)
    __shared__ float B1[64];
    __shared__ ull W2p[64];         // (W2[j][0], W2[j][1]) pairs
    __shared__ float B2[2];
    int tid = threadIdx.x;
    for (int i = tid; i < 256; i += 256) W1B[i] = mW1[32 * 64 + i];
    if (tid < 64) B1[tid] = mb1[tid];
    if (tid < 128) ((float*)W2p)[tid] = mW2[tid];
    if (tid < 2) B2[tid] = mb2[tid];
    __syncthreads();

    int e = blockIdx.x * 256 + tid;
    if (e >= EE) return;
    int s = src[e], d = dst[e];

    float4 a4 = *(const float4*)(ex2 + (size_t)e * 4);
    float4 dn = *(const float4*)(den2 + (size_t)d * 4);
    float al0 = a4.x / (dn.x + 1e-16f);
    float al1 = a4.y / (dn.y + 1e-16f);
    float al2 = a4.z / (dn.z + 1e-16f);
    float al3 = a4.w / (dn.w + 1e-16f);

    const uint4* PQh = (const uint4*)PQ;  // 16 uint4 per node row (128 halves)
    size_t bs = (size_t)s * 16;           // P: cols 0..63  -> uint4 idx 0..7
    size_t bd = (size_t)d * 16 + 8;       // Q: cols 64..127 -> uint4 idx 0..7

    ull o2 = pack2(B2[0], B2[1]);
#pragma unroll
    for (int qq = 0; qq < 8; qq++) {
        uint4 ph = PQh[bs + qq];
        uint4 qh = PQh[bd + qq];
        const __half2* php = (const __half2*)&ph;
        const __half2* qhp = (const __half2*)&qh;
#pragma unroll
        for (int u2 = 0; u2 < 4; u2++) {
            float2 pf = __half22float2(php[u2]);
            float2 qf = __half22float2(qhp[u2]);
#pragma unroll
            for (int v = 0; v < 2; v++) {
                int j = 8 * qq + 2 * u2 + v;
                float hv = B1[j] + (v ? pf.y : pf.x) + (v ? qf.y : qf.x);
                hv = fmaf(al0, W1B[j], hv);
                hv = fmaf(al1, W1B[64 + j], hv);
                hv = fmaf(al2, W1B[128 + j], hv);
                hv = fmaf(al3, W1B[192 + j], hv);
                hv = fmaxf(hv, 0.f);
                o2 = ffma2(pack2(hv, hv), W2p[j], o2);
            }
        }
    }
    float o0, o1;
    unpack2(o2, o0, o1);
    ((float2*)eo)[e] = make_float2(o0, o1);
}

// ---------------- launch ----------------
extern "C" void kernel_launch(void* const* d_in, const int* in_sizes, int n_in,
                              void* d_out, int out_size) {
    const float* x    = (const float*)d_in[0];
    const int*   ei   = (const int*)d_in[1];
    const float* W1   = (const float*)d_in[4];
    const float* a1s  = (const float*)d_in[5];
    const float* a1d  = (const float*)d_in[6];
    const float* b1   = (const float*)d_in[7];
    const float* W3   = (const float*)d_in[8];
    const float* a3s  = (const float*)d_in[9];
    const float* a3d  = (const float*)d_in[10];
    const float* b3   = (const float*)d_in[11];
    const float* mW1  = (const float*)d_in[12];
    const float* mb1  = (const float*)d_in[13];
    const float* mW2  = (const float*)d_in[14];
    const float* mb2  = (const float*)d_in[15];

    const int* src = ei;
    const int* dst = ei + EE;

    float* out_nodes = (float*)d_out;             // N*32
    float* out_edges = (float*)d_out + NN * 32;   // E*2

    __half *p_xl1h, *p_xl2h, *p_pqh;
    float *p_x2, *p_a1s, *p_a1d, *p_a2s, *p_a2d, *p_ex2;
    float *p_den2, *p_wpq;
    int *p_deg, *p_ptr, *p_pos, *p_bsum;
    int2 *p_eid;
    cudaGetSymbolAddress((void**)&p_xl1h, g_xl1h);
    cudaGetSymbolAddress((void**)&p_xl2h, g_xl2h);
    cudaGetSymbolAddress((void**)&p_x2,  g_x2);
    cudaGetSymbolAddress((void**)&p_a1s, g_a1s);
    cudaGetSymbolAddress((void**)&p_a1d, g_a1d);
    cudaGetSymbolAddress((void**)&p_a2s, g_a2s);
    cudaGetSymbolAddress((void**)&p_a2d, g_a2d);
    cudaGetSymbolAddress((void**)&p_ex2, g_ex2);
    cudaGetSymbolAddress((void**)&p_den2, g_den2);
    cudaGetSymbolAddress((void**)&p_pqh, g_pqh);
    cudaGetSymbolAddress((void**)&p_wpq, g_wpq);
    cudaGetSymbolAddress((void**)&p_deg, g_deg);
    cudaGetSymbolAddress((void**)&p_ptr, g_ptr);
    cudaGetSymbolAddress((void**)&p_pos, g_pos);
    cudaGetSymbolAddress((void**)&p_bsum, g_bsum);
    cudaGetSymbolAddress((void**)&p_eid, g_eid);

    static cudaStream_t s2 = nullptr;
    static cudaEvent_t evFork = nullptr, evJoin = nullptr;
    if (!s2) {
        cudaStreamCreateWithFlags(&s2, cudaStreamNonBlocking);
        cudaEventCreateWithFlags(&evFork, cudaEventDisableTiming);
        cudaEventCreateWithFlags(&evJoin, cudaEventDisableTiming);
    }

    const int NB = (NN + 511) / 512;  // 98
    const int SMEM1 = (128 * SA + 128 * SB + 512) * 4;  // 204800 B

    cudaMemsetAsync(p_deg, 0, (size_t)NN * 4);
    cudaEventRecord(evFork, 0);                       // fork point
    cudaStreamWaitEvent(s2, evFork, 0);

    // main stream: CSR build chain
    hist_kernel<<<(EE + 255) / 256, 256>>>(dst, p_deg);
    scanA_kernel<<<NB, 512>>>(p_deg, p_ptr, p_bsum);
    scanB_kernel<<<1, 128>>>(p_bsum, NB);

    // side stream: gemm1 tf32 + repack
    cudaFuncSetAttribute((const void*)gemm1_tf32,
                         cudaFuncAttributeMaxDynamicSharedMemorySize, SMEM1);
    gemm1_tf32<<<(NN + 127) / 128, 256, SMEM1, s2>>>(
        x, W1, p_xl1h, a1s, a1d, p_a1s, p_a1d, NN);
    repack_wpq<<<(32 * 128 + 255) / 256, 256, 0, s2>>>(mW1, p_wpq);
    cudaEventRecord(evJoin, s2);

    scanC_kernel<<<NB, 512>>>(p_ptr, p_bsum, p_pos);
    scatter_kernel<<<(EE + 255) / 256, 256>>>(src, dst, p_pos, p_eid);

    cudaStreamWaitEvent(0, evJoin, 0);                // join

    // Layer 1 aggregation (fused exp/den/finalize)
    agg_csr64<<<(NN + 7) / 8, 256>>>(p_eid, p_ptr, p_deg, p_xl1h,
                                     p_a1s, p_a1d, b1, p_x2);

    // Layer 2
    cudaFuncSetAttribute((const void*)gemm_xw<64, 128, 128, 256, 8, true, true>,
                         cudaFuncAttributeMaxDynamicSharedMemorySize, 65536);
    gemm_xw<64, 128, 128, 256, 8, true, true><<<(NN + 127) / 128, 256, 65536>>>(
        p_x2, W3, p_xl2h, a3s, a3d, p_a2s, p_a2d, NN);
    agg_csr32<<<(NN + 7) / 8, 256>>>(p_eid, p_ptr, p_deg, p_xl2h,
                                     p_a2s, p_a2d, b3, out_nodes,
                                     p_ex2, p_den2);

    // Edge MLP: per-node P/Q precompute (fp16 out), then light per-edge kernel
    cudaFuncSetAttribute((const void*)gemm_xw<32, 128, 128, 256, 8, true, false>,
                         cudaFuncAttributeMaxDynamicSharedMemorySize, 32768);
    gemm_xw<32, 128, 128, 256, 8, true, false><<<(NN + 127) / 128, 256, 32768>>>(
        out_nodes, p_wpq, p_pqh, nullptr, nullptr, nullptr, nullptr, NN);
    edge_mlp2_kernel<<<(EE + 255) / 256, 256>>>(src, dst, p_pqh, p_ex2, p_den2,
                                                mW1, mb1, mW2, mb2, out_edges);
}